// round 6
// baseline (speedup 1.0000x reference)
#include <cuda_runtime.h>
#include <cstdint>

#define NN      12000
#define HID     32
#define TSTEPS  50
#define TM      128
#define KSPLIT  3
#define KITEM   4000             // K per work item (KSPLIT*KITEM == NN)
#define NCHUNK  125              // KITEM / 32
#define NBLK    94               // ceil(12000/128)
#define NITEMS  (NBLK * KSPLIT)  // 282 CTAs, one item each (all co-resident)
#define NSTAGES 5
#define STAGE_BYTES 20480        // A: 128*32*4 = 16384  +  B: 32*32*4 = 4096
#define SMEM_REQ (NSTAGES * STAGE_BYTES)
#define SROWS   48               // support rows per CTA
#define SCTAS   250              // 250*48 == 12000

__device__ float    g_suppT[HID * NN];          // support^T, tf32-rounded
__device__ float    g_part[KSPLIT * NN * HID];  // split-K partials
__device__ unsigned g_bar;                      // global barrier (epoch-counting)
__device__ unsigned g_done[NBLK];               // per-row-block arrival counters

// ---------------------------------------------------------------------------
// cp.async stage loads: line-complete per warp-op (whole 128B lines).
// ---------------------------------------------------------------------------
__device__ __forceinline__ void load_A(uint32_t sbase, const float* __restrict__ adj,
                                       int row0, int gk, int tid) {
    int q  = tid & 7;
    int rb = tid >> 3;
#pragma unroll
    for (int i = 0; i < 4; i++) {
        int r = i * 32 + rb;
        const float* src = adj + (long long)(row0 + r) * NN + gk + q * 4;
        uint32_t dst = sbase + r * 128 + (uint32_t)((q ^ (r & 7)) << 4);
        int sz = (row0 + r < NN) ? 16 : 0;
        asm volatile("cp.async.cg.shared.global.L2::256B [%0], [%1], 16, %2;\n"
                     :: "r"(dst), "l"(src), "r"(sz));
    }
}

__device__ __forceinline__ void load_B(uint32_t sbase, int gk, int tid) {
    int q = tid & 7;
    int c = tid >> 3;
    const float* src = g_suppT + (long long)c * NN + gk + q * 4;
    uint32_t dst = sbase + 16384 + c * 128 + (uint32_t)((q ^ (c & 7)) << 4);
    asm volatile("cp.async.cg.shared.global.L2::256B [%0], [%1], 16;\n"
                 :: "r"(dst), "l"(src));
}

// ---------------------------------------------------------------------------
// Fused kernel: [A-prologue | support | global barrier | B-prologue |
//                GEMM mainloop | partials | last-CTA reduce+bias+relu]
// ---------------------------------------------------------------------------
__global__ void __launch_bounds__(256, 2)
fused_kernel(const float* __restrict__ adj,
             const float* __restrict__ t,
             const float* __restrict__ z,
             const float* __restrict__ treat,
             const float* __restrict__ W,
             const float* __restrict__ bias,
             float* __restrict__ out) {
    extern __shared__ char dsm[];
    uint32_t sbase0 = (uint32_t)__cvta_generic_to_shared(dsm);
    int tid  = threadIdx.x;
    int warp = tid >> 5;
    int lane = tid & 31;
    int g    = lane >> 2;
    int tg   = lane & 3;
    int bx   = blockIdx.x;

    int blk  = bx / KSPLIT;
    int kc   = bx - blk * KSPLIT;
    int row0 = blk * TM;
    int k0   = kc * KITEM;

    // ---- A-only prologue: groups G0..G3 (adj is independent of support) ----
#pragma unroll
    for (int p = 0; p < NSTAGES - 1; p++) {
        load_A(sbase0 + p * STAGE_BYTES, adj, row0, k0 + p * 32, tid);
        asm volatile("cp.async.commit_group;\n" ::: "memory");
    }

    // ---- support phase (overlaps the A loads above) ----
    if (bx < SCTAS) {
        // scratch lives in stage 4's A region (untouched until after barrier)
        float (*S)[33] = (float (*)[33])(dsm + 4 * STAGE_BYTES);          // 48x33
        float* Ws      = (float*)(dsm + 4 * STAGE_BYTES + 8192);          // 33x32
        for (int i = tid; i < 33 * 32; i += 256) Ws[i] = W[i];
        __syncthreads();

        int a_idx = (int)(t[0] * (float)(TSTEPS - 1));
        a_idx = min(max(a_idx, 0), TSTEPS - 1);

        int base = bx * SROWS;
        int r0   = warp * 6;                 // 6 rows per warp, 8 warps = 48
        float zv[6], acc[6];
#pragma unroll
        for (int j = 0; j < 6; j++) {
            int row = base + r0 + j;
            zv[j]  = z[row * 32 + lane];
            acc[j] = treat[row * TSTEPS + a_idx] * Ws[32 * 32 + lane];
        }
#pragma unroll
        for (int k = 0; k < 32; k++) {
            float w = Ws[k * 32 + lane];
#pragma unroll
            for (int j = 0; j < 6; j++) {
                float zk = __shfl_sync(0xffffffffu, zv[j], k);
                acc[j] = fmaf(zk, w, acc[j]);
            }
        }
#pragma unroll
        for (int j = 0; j < 6; j++) {
            uint32_t bits;
            asm("cvt.rna.tf32.f32 %0, %1;" : "=r"(bits) : "f"(acc[j]));
            S[r0 + j][lane] = __uint_as_float(bits);
        }
        __syncthreads();
        // coalesced transposed store: 48*32 = 1536 floats, 6 per thread
#pragma unroll
        for (int j = 0; j < 6; j++) {
            int idx = tid + 256 * j;
            int col = idx / SROWS;
            int r   = idx - col * SROWS;
            g_suppT[col * NN + base + r] = S[r][col];
        }
    }

    // ---- global barrier (all 282 CTAs co-resident; epoch counting) ----
    __syncthreads();
    if (tid == 0) {
        unsigned old;
        asm volatile("membar.gl;\n" ::: "memory");
        asm volatile("atom.release.gpu.add.u32 %0, [%1], 1;"
                     : "=r"(old) : "l"(&g_bar) : "memory");
        unsigned target = (old / NITEMS + 1u) * NITEMS;
        unsigned cur;
        do {
            asm volatile("ld.acquire.gpu.u32 %0, [%1];"
                         : "=r"(cur) : "l"(&g_bar) : "memory");
        } while (cur < target);
    }
    __syncthreads();

    // ---- B prologue: groups G4..G7 ----
#pragma unroll
    for (int p = 0; p < NSTAGES - 1; p++) {
        load_B(sbase0 + p * STAGE_BYTES, k0 + p * 32, tid);
        asm volatile("cp.async.commit_group;\n" ::: "memory");
    }

    // ---- GEMM mainloop ----
    float acc[4][4];
#pragma unroll
    for (int n = 0; n < 4; n++)
#pragma unroll
        for (int i = 0; i < 4; i++) acc[n][i] = 0.f;

    const uint32_t aoff = (uint32_t)(warp * 16 + g) * 128 + tg * 4;
    const uint32_t boff = 16384u + (uint32_t)g * 128 + tg * 4;

    for (int c = 0; c < NCHUNK; c++) {
        asm volatile("cp.async.wait_group 3;\n" ::: "memory");
        __syncthreads();

        if (c + NSTAGES - 1 < NCHUNK) {
            uint32_t sb = sbase0 + ((c + NSTAGES - 1) % NSTAGES) * STAGE_BYTES;
            load_A(sb, adj, row0, k0 + (c + NSTAGES - 1) * 32, tid);
            load_B(sb, k0 + (c + NSTAGES - 1) * 32, tid);
        }
        asm volatile("cp.async.commit_group;\n" ::: "memory");

        const char* st = dsm + (c % NSTAGES) * STAGE_BYTES;
#pragma unroll
        for (int ks = 0; ks < 4; ks++) {
            uint32_t q0 = (uint32_t)(((2 * ks) ^ g) << 4);
            uint32_t q1 = (uint32_t)(((2 * ks + 1) ^ g) << 4);

            uint32_t a0 = *(const uint32_t*)(st + aoff + q0);
            uint32_t a2 = *(const uint32_t*)(st + aoff + q1);
            uint32_t a1 = *(const uint32_t*)(st + aoff + 1024 + q0);
            uint32_t a3 = *(const uint32_t*)(st + aoff + 1024 + q1);
#pragma unroll
            for (int nt = 0; nt < 4; nt++) {
                uint32_t b0 = *(const uint32_t*)(st + boff + nt * 1024 + q0);
                uint32_t b1 = *(const uint32_t*)(st + boff + nt * 1024 + q1);
                asm volatile(
                    "mma.sync.aligned.m16n8k8.row.col.f32.tf32.tf32.f32 "
                    "{%0,%1,%2,%3}, {%4,%5,%6,%7}, {%8,%9}, {%0,%1,%2,%3};\n"
                    : "+f"(acc[nt][0]), "+f"(acc[nt][1]),
                      "+f"(acc[nt][2]), "+f"(acc[nt][3])
                    : "r"(a0), "r"(a1), "r"(a2), "r"(a3), "r"(b0), "r"(b1));
            }
        }
    }

    // ---- write split-K partial ----
    float* part = g_part + (long long)kc * (NN * HID);
    int r_lo = row0 + warp * 16 + g;
    int r_hi = r_lo + 8;
#pragma unroll
    for (int nt = 0; nt < 4; nt++) {
        int colb = nt * 8 + 2 * tg;
        if (r_lo < NN)
            *(float2*)(part + (long long)r_lo * HID + colb) =
                make_float2(acc[nt][0], acc[nt][1]);
        if (r_hi < NN)
            *(float2*)(part + (long long)r_hi * HID + colb) =
                make_float2(acc[nt][2], acc[nt][3]);
    }

    // ---- last CTA of this row-block does the deterministic reduce ----
    __syncthreads();
    __shared__ int s_last;
    if (tid == 0) {
        unsigned old;
        asm volatile("membar.gl;\n" ::: "memory");
        asm volatile("atom.acq_rel.gpu.add.u32 %0, [%1], 1;"
                     : "=r"(old) : "l"(&g_done[blk]) : "memory");
        s_last = ((old % 3u) == 2u);
    }
    __syncthreads();

    if (s_last) {
        const float4* p0 = (const float4*)(g_part + (long long)row0 * HID);
        const float4* p1 = (const float4*)(g_part + (long long)(NN * HID) +
                                           (long long)row0 * HID);
        const float4* p2 = (const float4*)(g_part + 2LL * (NN * HID) +
                                           (long long)row0 * HID);
        const float4* bv = (const float4*)bias;
#pragma unroll
        for (int j = 0; j < 4; j++) {
            int idx = tid + 256 * j;          // float4 index in 128x32 tile
            int row = row0 + (idx >> 3);
            if (row < NN) {
                float4 a = p0[idx], bq = p1[idx], cq = p2[idx];
                float4 bb = bv[idx & 7];
                float4 r;
                r.x = fmaxf(a.x + bq.x + cq.x + bb.x, 0.f);
                r.y = fmaxf(a.y + bq.y + cq.y + bb.y, 0.f);
                r.z = fmaxf(a.z + bq.z + cq.z + bb.z, 0.f);
                r.w = fmaxf(a.w + bq.w + cq.w + bb.w, 0.f);
                ((float4*)out)[(long long)row * 8 + (idx & 7)] = r;
            }
        }
    }
}

// ---------------------------------------------------------------------------
extern "C" void kernel_launch(void* const* d_in, const int* in_sizes, int n_in,
                              void* d_out, int out_size) {
    (void)in_sizes; (void)n_in; (void)out_size;
    const float* t     = (const float*)d_in[0];
    const float* z     = (const float*)d_in[1];
    const float* adj   = (const float*)d_in[2];
    const float* treat = (const float*)d_in[3];
    const float* W     = (const float*)d_in[4];
    const float* b     = (const float*)d_in[5];
    float* out = (float*)d_out;

    cudaFuncSetAttribute(fused_kernel,
                         cudaFuncAttributeMaxDynamicSharedMemorySize, SMEM_REQ);

    fused_kernel<<<NITEMS, 256, SMEM_REQ>>>(adj, t, z, treat, W, b, out);
}

// round 7
// speedup vs baseline: 1.0091x; 1.0091x over previous
#include <cuda_runtime.h>
#include <cstdint>

#define NN      12000
#define HID     32
#define TSTEPS  50
#define TM      128
#define KSPLIT  3
#define KITEM   4000             // K per work item (KSPLIT*KITEM == NN)
#define NCHUNK  125              // KITEM / 32
#define NBLK    94               // ceil(12000/128)
#define NITEMS  (NBLK * KSPLIT)  // 282 CTAs, one item each
#define NSTAGES 5
#define STAGE_BYTES 20480        // A: 128*32*4 = 16384  +  B: 32*32*4 = 4096
#define SMEM_REQ (NSTAGES * STAGE_BYTES)

__device__ float    g_suppT[HID * NN];          // support^T, tf32-rounded
__device__ float    g_part[KSPLIT * NN * HID];  // split-K partials
__device__ unsigned g_done[NBLK];               // per-row-block arrival counters

// ---------------------------------------------------------------------------
// Kernel 1: support = [z | a_t] @ W, transposed + tf32-rounded output.
// Triggers PDL dependents as soon as its stores are globally visible.
// ---------------------------------------------------------------------------
__global__ void support_kernel(const float* __restrict__ t,
                               const float* __restrict__ z,
                               const float* __restrict__ treat,
                               const float* __restrict__ W) {
    __shared__ float Ws[33 * 32];
    __shared__ float S[32][33];    // stride 33 -> conflict-free transpose
    int tid = threadIdx.x;
    for (int i = tid; i < 33 * 32; i += blockDim.x) Ws[i] = W[i];
    __syncthreads();

    int a_idx = (int)(t[0] * (float)(TSTEPS - 1));
    a_idx = min(max(a_idx, 0), TSTEPS - 1);

    int lane = tid & 31;
    int warp = tid >> 5;
    int row0 = blockIdx.x * 32;         // grid = 375, 375*32 == 12000
    int r0   = warp * 4;

    float zv[4], acc[4];
#pragma unroll
    for (int j = 0; j < 4; j++) {
        int row = row0 + r0 + j;
        zv[j]  = z[row * 32 + lane];
        acc[j] = treat[row * TSTEPS + a_idx] * Ws[32 * 32 + lane];
    }
#pragma unroll
    for (int k = 0; k < 32; k++) {
        float w = Ws[k * 32 + lane];
#pragma unroll
        for (int j = 0; j < 4; j++) {
            float zk = __shfl_sync(0xffffffffu, zv[j], k);
            acc[j] = fmaf(zk, w, acc[j]);
        }
    }
#pragma unroll
    for (int j = 0; j < 4; j++) {
        uint32_t bits;
        asm("cvt.rna.tf32.f32 %0, %1;" : "=r"(bits) : "f"(acc[j]));
        S[r0 + j][lane] = __uint_as_float(bits);
    }
    __syncthreads();

#pragma unroll
    for (int j = 0; j < 4; j++) {
        int idx = tid + 256 * j;
        int col = idx >> 5;
        int r   = idx & 31;
        g_suppT[col * NN + row0 + r] = S[r][col];
    }

    // make stores visible, then allow the dependent GEMM's wait to release
    asm volatile("membar.gl;\n" ::: "memory");
    asm volatile("griddepcontrol.launch_dependents;\n" ::: "memory");
}

// ---------------------------------------------------------------------------
// cp.async stage loads: line-complete per warp-op (whole 128B lines).
// ---------------------------------------------------------------------------
__device__ __forceinline__ void load_A(uint32_t sbase, const float* __restrict__ adj,
                                       int row0, int gk, int tid) {
    int q  = tid & 7;
    int rb = tid >> 3;
#pragma unroll
    for (int i = 0; i < 4; i++) {
        int r = i * 32 + rb;
        const float* src = adj + (long long)(row0 + r) * NN + gk + q * 4;
        uint32_t dst = sbase + r * 128 + (uint32_t)((q ^ (r & 7)) << 4);
        int sz = (row0 + r < NN) ? 16 : 0;
        asm volatile("cp.async.cg.shared.global.L2::256B [%0], [%1], 16, %2;\n"
                     :: "r"(dst), "l"(src), "r"(sz));
    }
}

__device__ __forceinline__ void load_B(uint32_t sbase, int gk, int tid) {
    int q = tid & 7;
    int c = tid >> 3;
    const float* src = g_suppT + (long long)c * NN + gk + q * 4;
    uint32_t dst = sbase + 16384 + c * 128 + (uint32_t)((q ^ (c & 7)) << 4);
    asm volatile("cp.async.cg.shared.global.L2::256B [%0], [%1], 16;\n"
                 :: "r"(dst), "l"(src));
}

// ---------------------------------------------------------------------------
// Kernel 2: tf32 mma.sync GEMM + fused deterministic split-K reduce tail.
// PDL: A-prologue issues before griddepcontrol.wait; B waits for support.
// ---------------------------------------------------------------------------
__global__ void __launch_bounds__(256, 2)
gemm_mma_kernel(const float* __restrict__ adj,
                const float* __restrict__ bias,
                float* __restrict__ out) {
    extern __shared__ char dsm[];
    uint32_t sbase0 = (uint32_t)__cvta_generic_to_shared(dsm);
    int tid  = threadIdx.x;
    int warp = tid >> 5;
    int lane = tid & 31;
    int g    = lane >> 2;
    int tg   = lane & 3;

    int blk  = blockIdx.x / KSPLIT;
    int kc   = blockIdx.x - blk * KSPLIT;
    int row0 = blk * TM;
    int k0   = kc * KITEM;

    // ---- A-only prologue (independent of support): groups G0..G3 ----
#pragma unroll
    for (int p = 0; p < NSTAGES - 1; p++) {
        load_A(sbase0 + p * STAGE_BYTES, adj, row0, k0 + p * 32, tid);
        asm volatile("cp.async.commit_group;\n" ::: "memory");
    }

    // ---- wait for support kernel's g_suppT to be visible ----
    asm volatile("griddepcontrol.wait;\n" ::: "memory");

    // ---- B prologue: groups G4..G7 ----
#pragma unroll
    for (int p = 0; p < NSTAGES - 1; p++) {
        load_B(sbase0 + p * STAGE_BYTES, k0 + p * 32, tid);
        asm volatile("cp.async.commit_group;\n" ::: "memory");
    }

    float acc[4][4];
#pragma unroll
    for (int n = 0; n < 4; n++)
#pragma unroll
        for (int i = 0; i < 4; i++) acc[n][i] = 0.f;

    const uint32_t aoff = (uint32_t)(warp * 16 + g) * 128 + tg * 4;
    const uint32_t boff = 16384u + (uint32_t)g * 128 + tg * 4;

    for (int c = 0; c < NCHUNK; c++) {
        asm volatile("cp.async.wait_group 3;\n" ::: "memory");
        __syncthreads();

        if (c + NSTAGES - 1 < NCHUNK) {
            uint32_t sb = sbase0 + ((c + NSTAGES - 1) % NSTAGES) * STAGE_BYTES;
            load_A(sb, adj, row0, k0 + (c + NSTAGES - 1) * 32, tid);
            load_B(sb, k0 + (c + NSTAGES - 1) * 32, tid);
        }
        asm volatile("cp.async.commit_group;\n" ::: "memory");

        const char* st = dsm + (c % NSTAGES) * STAGE_BYTES;
#pragma unroll
        for (int ks = 0; ks < 4; ks++) {
            uint32_t q0 = (uint32_t)(((2 * ks) ^ g) << 4);
            uint32_t q1 = (uint32_t)(((2 * ks + 1) ^ g) << 4);

            uint32_t a0 = *(const uint32_t*)(st + aoff + q0);
            uint32_t a2 = *(const uint32_t*)(st + aoff + q1);
            uint32_t a1 = *(const uint32_t*)(st + aoff + 1024 + q0);
            uint32_t a3 = *(const uint32_t*)(st + aoff + 1024 + q1);
#pragma unroll
            for (int nt = 0; nt < 4; nt++) {
                uint32_t b0 = *(const uint32_t*)(st + boff + nt * 1024 + q0);
                uint32_t b1 = *(const uint32_t*)(st + boff + nt * 1024 + q1);
                asm volatile(
                    "mma.sync.aligned.m16n8k8.row.col.f32.tf32.tf32.f32 "
                    "{%0,%1,%2,%3}, {%4,%5,%6,%7}, {%8,%9}, {%0,%1,%2,%3};\n"
                    : "+f"(acc[nt][0]), "+f"(acc[nt][1]),
                      "+f"(acc[nt][2]), "+f"(acc[nt][3])
                    : "r"(a0), "r"(a1), "r"(a2), "r"(a3), "r"(b0), "r"(b1));
            }
        }
    }

    // ---- write split-K partial ----
    float* part = g_part + (long long)kc * (NN * HID);
    int r_lo = row0 + warp * 16 + g;
    int r_hi = r_lo + 8;
#pragma unroll
    for (int nt = 0; nt < 4; nt++) {
        int colb = nt * 8 + 2 * tg;
        if (r_lo < NN)
            *(float2*)(part + (long long)r_lo * HID + colb) =
                make_float2(acc[nt][0], acc[nt][1]);
        if (r_hi < NN)
            *(float2*)(part + (long long)r_hi * HID + colb) =
                make_float2(acc[nt][2], acc[nt][3]);
    }

    // ---- last CTA of this row-block: deterministic reduce + bias + relu ----
    __syncthreads();
    __shared__ int s_last;
    if (tid == 0) {
        unsigned old;
        asm volatile("membar.gl;\n" ::: "memory");
        asm volatile("atom.acq_rel.gpu.add.u32 %0, [%1], 1;"
                     : "=r"(old) : "l"(&g_done[blk]) : "memory");
        s_last = ((old % 3u) == 2u);
    }
    __syncthreads();

    if (s_last) {
        const float4* p0 = (const float4*)(g_part + (long long)row0 * HID);
        const float4* p1 = (const float4*)(g_part + (long long)(NN * HID) +
                                           (long long)row0 * HID);
        const float4* p2 = (const float4*)(g_part + 2LL * (NN * HID) +
                                           (long long)row0 * HID);
        const float4* bv = (const float4*)bias;
#pragma unroll
        for (int j = 0; j < 4; j++) {
            int idx = tid + 256 * j;          // float4 index in 128x32 tile
            int row = row0 + (idx >> 3);
            if (row < NN) {
                float4 a = p0[idx], bq = p1[idx], cq = p2[idx];
                float4 bb = bv[idx & 7];
                float4 r;
                r.x = fmaxf(a.x + bq.x + cq.x + bb.x, 0.f);
                r.y = fmaxf(a.y + bq.y + cq.y + bb.y, 0.f);
                r.z = fmaxf(a.z + bq.z + cq.z + bb.z, 0.f);
                r.w = fmaxf(a.w + bq.w + cq.w + bb.w, 0.f);
                ((float4*)out)[(long long)row * 8 + (idx & 7)] = r;
            }
        }
    }
}

// ---------------------------------------------------------------------------
extern "C" void kernel_launch(void* const* d_in, const int* in_sizes, int n_in,
                              void* d_out, int out_size) {
    (void)in_sizes; (void)n_in; (void)out_size;
    const float* t     = (const float*)d_in[0];
    const float* z     = (const float*)d_in[1];
    const float* adj   = (const float*)d_in[2];
    const float* treat = (const float*)d_in[3];
    const float* W     = (const float*)d_in[4];
    const float* b     = (const float*)d_in[5];
    float* out = (float*)d_out;

    cudaFuncSetAttribute(gemm_mma_kernel,
                         cudaFuncAttributeMaxDynamicSharedMemorySize, SMEM_REQ);

    support_kernel<<<NN / 32, 256>>>(t, z, treat, W);

    cudaLaunchConfig_t cfg = {};
    cfg.gridDim  = dim3(NITEMS, 1, 1);
    cfg.blockDim = dim3(256, 1, 1);
    cfg.dynamicSmemBytes = SMEM_REQ;
    cfg.stream = 0;
    cudaLaunchAttribute attrs[1];
    attrs[0].id = cudaLaunchAttributeProgrammaticStreamSerialization;
    attrs[0].val.programmaticStreamSerializationAllowed = 1;
    cfg.attrs = attrs;
    cfg.numAttrs = 1;
    cudaLaunchKernelEx(&cfg, gemm_mma_kernel, adj, (const float*)b, out);
}

// round 8
// speedup vs baseline: 1.2454x; 1.2341x over previous
#include <cuda_runtime.h>
#include <cstdint>

#define NN      12000
#define HID     32
#define TSTEPS  50
#define TM      128
#define KSPLIT  3
#define KITEM   4000             // K per work item (KSPLIT*KITEM == NN)
#define NCHUNK  125              // KITEM / 32
#define NBLK    94               // ceil(12000/128)
#define NITEMS  (NBLK * KSPLIT)  // 282 CTAs, one item each
#define NSTAGES 5
#define STAGE_BYTES 20480        // A: 128*32*4 = 16384  +  B: 32*32*4 = 4096
#define SMEM_REQ (NSTAGES * STAGE_BYTES)

__device__ float g_suppT[HID * NN];           // support^T: [32][12000], tf32-rounded
__device__ float g_part[KSPLIT * NN * HID];   // split-K partials (deterministic)

// ---------------------------------------------------------------------------
// Kernel 1: support = [z | a_t] @ W, transposed + tf32-rounded output.
// Fires PDL trigger once stores are globally visible.
// ---------------------------------------------------------------------------
__global__ void support_kernel(const float* __restrict__ t,
                               const float* __restrict__ z,
                               const float* __restrict__ treat,
                               const float* __restrict__ W) {
    __shared__ float Ws[33 * 32];
    __shared__ float S[32][33];    // stride 33 -> conflict-free transpose
    int tid = threadIdx.x;
    for (int i = tid; i < 33 * 32; i += blockDim.x) Ws[i] = W[i];
    __syncthreads();

    int a_idx = (int)(t[0] * (float)(TSTEPS - 1));
    a_idx = min(max(a_idx, 0), TSTEPS - 1);

    int lane = tid & 31;
    int warp = tid >> 5;
    int row0 = blockIdx.x * 32;         // grid = 375, 375*32 == 12000
    int r0   = warp * 4;

    float zv[4], acc[4];
#pragma unroll
    for (int j = 0; j < 4; j++) {
        int row = row0 + r0 + j;
        zv[j]  = z[row * 32 + lane];
        acc[j] = treat[row * TSTEPS + a_idx] * Ws[32 * 32 + lane];
    }
#pragma unroll
    for (int k = 0; k < 32; k++) {
        float w = Ws[k * 32 + lane];
#pragma unroll
        for (int j = 0; j < 4; j++) {
            float zk = __shfl_sync(0xffffffffu, zv[j], k);
            acc[j] = fmaf(zk, w, acc[j]);
        }
    }
#pragma unroll
    for (int j = 0; j < 4; j++) {
        uint32_t bits;
        asm("cvt.rna.tf32.f32 %0, %1;" : "=r"(bits) : "f"(acc[j]));
        S[r0 + j][lane] = __uint_as_float(bits);
    }
    __syncthreads();

#pragma unroll
    for (int j = 0; j < 4; j++) {
        int idx = tid + 256 * j;
        int col = idx >> 5;
        int r   = idx & 31;
        g_suppT[col * NN + row0 + r] = S[r][col];
    }

    asm volatile("membar.gl;\n" ::: "memory");
    asm volatile("griddepcontrol.launch_dependents;\n" ::: "memory");
}

// ---------------------------------------------------------------------------
// cp.async stage loads: line-complete per warp-op (whole 128B lines).
// ---------------------------------------------------------------------------
__device__ __forceinline__ void load_A(uint32_t sbase, const float* __restrict__ adj,
                                       int row0, int gk, int tid) {
    int q  = tid & 7;
    int rb = tid >> 3;
#pragma unroll
    for (int i = 0; i < 4; i++) {
        int r = i * 32 + rb;
        const float* src = adj + (long long)(row0 + r) * NN + gk + q * 4;
        uint32_t dst = sbase + r * 128 + (uint32_t)((q ^ (r & 7)) << 4);
        int sz = (row0 + r < NN) ? 16 : 0;
        asm volatile("cp.async.cg.shared.global.L2::256B [%0], [%1], 16, %2;\n"
                     :: "r"(dst), "l"(src), "r"(sz));
    }
}

__device__ __forceinline__ void load_B(uint32_t sbase, int gk, int tid) {
    int q = tid & 7;
    int c = tid >> 3;
    const float* src = g_suppT + (long long)c * NN + gk + q * 4;
    uint32_t dst = sbase + 16384 + c * 128 + (uint32_t)((q ^ (c & 7)) << 4);
    asm volatile("cp.async.cg.shared.global.L2::256B [%0], [%1], 16;\n"
                 :: "r"(dst), "l"(src));
}

// ---------------------------------------------------------------------------
// Kernel 2: tf32 mma.sync GEMM — body identical to the 103.2us round-5 build.
// Only change: A-prologue before griddepcontrol.wait, B-prologue after.
// ---------------------------------------------------------------------------
__global__ void __launch_bounds__(256, 2)
gemm_mma_kernel(const float* __restrict__ adj) {
    extern __shared__ char dsm[];
    uint32_t sbase0 = (uint32_t)__cvta_generic_to_shared(dsm);
    int tid  = threadIdx.x;
    int warp = tid >> 5;
    int lane = tid & 31;
    int g    = lane >> 2;
    int tg   = lane & 3;

    int blk  = blockIdx.x / KSPLIT;
    int kc   = blockIdx.x - blk * KSPLIT;
    int row0 = blk * TM;
    int k0   = kc * KITEM;

    // A-only prologue (adj independent of support): groups 1..4
#pragma unroll
    for (int p = 0; p < NSTAGES - 1; p++) {
        load_A(sbase0 + p * STAGE_BYTES, adj, row0, k0 + p * 32, tid);
        asm volatile("cp.async.commit_group;\n" ::: "memory");
    }

    asm volatile("griddepcontrol.wait;\n" ::: "memory");

    // B prologue: groups 5..8
#pragma unroll
    for (int p = 0; p < NSTAGES - 1; p++) {
        load_B(sbase0 + p * STAGE_BYTES, k0 + p * 32, tid);
        asm volatile("cp.async.commit_group;\n" ::: "memory");
    }

    float acc[4][4];
#pragma unroll
    for (int n = 0; n < 4; n++)
#pragma unroll
        for (int i = 0; i < 4; i++) acc[n][i] = 0.f;

    const uint32_t aoff = (uint32_t)(warp * 16 + g) * 128 + tg * 4;
    const uint32_t boff = 16384u + (uint32_t)g * 128 + tg * 4;

    for (int c = 0; c < NCHUNK; c++) {
        asm volatile("cp.async.wait_group 3;\n" ::: "memory");
        __syncthreads();

        if (c + NSTAGES - 1 < NCHUNK) {
            uint32_t sb = sbase0 + ((c + NSTAGES - 1) % NSTAGES) * STAGE_BYTES;
            load_A(sb, adj, row0, k0 + (c + NSTAGES - 1) * 32, tid);
            load_B(sb, k0 + (c + NSTAGES - 1) * 32, tid);
        }
        asm volatile("cp.async.commit_group;\n" ::: "memory");

        const char* st = dsm + (c % NSTAGES) * STAGE_BYTES;
#pragma unroll
        for (int ks = 0; ks < 4; ks++) {
            uint32_t q0 = (uint32_t)(((2 * ks) ^ g) << 4);
            uint32_t q1 = (uint32_t)(((2 * ks + 1) ^ g) << 4);

            uint32_t a0 = *(const uint32_t*)(st + aoff + q0);
            uint32_t a2 = *(const uint32_t*)(st + aoff + q1);
            uint32_t a1 = *(const uint32_t*)(st + aoff + 1024 + q0);
            uint32_t a3 = *(const uint32_t*)(st + aoff + 1024 + q1);
#pragma unroll
            for (int nt = 0; nt < 4; nt++) {
                uint32_t b0 = *(const uint32_t*)(st + boff + nt * 1024 + q0);
                uint32_t b1 = *(const uint32_t*)(st + boff + nt * 1024 + q1);
                asm volatile(
                    "mma.sync.aligned.m16n8k8.row.col.f32.tf32.tf32.f32 "
                    "{%0,%1,%2,%3}, {%4,%5,%6,%7}, {%8,%9}, {%0,%1,%2,%3};\n"
                    : "+f"(acc[nt][0]), "+f"(acc[nt][1]),
                      "+f"(acc[nt][2]), "+f"(acc[nt][3])
                    : "r"(a0), "r"(a1), "r"(a2), "r"(a3), "r"(b0), "r"(b1));
            }
        }
    }

    float* part = g_part + (long long)kc * (NN * HID);
    int r_lo = row0 + warp * 16 + g;
    int r_hi = r_lo + 8;
#pragma unroll
    for (int nt = 0; nt < 4; nt++) {
        int colb = nt * 8 + 2 * tg;
        if (r_lo < NN)
            *(float2*)(part + (long long)r_lo * HID + colb) =
                make_float2(acc[nt][0], acc[nt][1]);
        if (r_hi < NN)
            *(float2*)(part + (long long)r_hi * HID + colb) =
                make_float2(acc[nt][2], acc[nt][3]);
    }
}

// ---------------------------------------------------------------------------
// Kernel 3: out = relu(sum_kc part[kc] + b)
// ---------------------------------------------------------------------------
__global__ void reduce_relu_kernel(float* __restrict__ out,
                                   const float* __restrict__ b) {
    int i4 = blockIdx.x * blockDim.x + threadIdx.x;
    if (i4 >= NN * HID / 4) return;
    const float4* p = (const float4*)g_part;
    float4 s = ((const float4*)b)[i4 & 7];
#pragma unroll
    for (int kc = 0; kc < KSPLIT; kc++) {
        float4 v = p[(long long)kc * (NN * HID / 4) + i4];
        s.x += v.x; s.y += v.y; s.z += v.z; s.w += v.w;
    }
    float4 r;
    r.x = fmaxf(s.x, 0.f);
    r.y = fmaxf(s.y, 0.f);
    r.z = fmaxf(s.z, 0.f);
    r.w = fmaxf(s.w, 0.f);
    ((float4*)out)[i4] = r;
}

// ---------------------------------------------------------------------------
extern "C" void kernel_launch(void* const* d_in, const int* in_sizes, int n_in,
                              void* d_out, int out_size) {
    (void)in_sizes; (void)n_in; (void)out_size;
    const float* t     = (const float*)d_in[0];
    const float* z     = (const float*)d_in[1];
    const float* adj   = (const float*)d_in[2];
    const float* treat = (const float*)d_in[3];
    const float* W     = (const float*)d_in[4];
    const float* b     = (const float*)d_in[5];
    float* out = (float*)d_out;

    cudaFuncSetAttribute(gemm_mma_kernel,
                         cudaFuncAttributeMaxDynamicSharedMemorySize, SMEM_REQ);

    support_kernel<<<NN / 32, 256>>>(t, z, treat, W);

    cudaLaunchConfig_t cfg = {};
    cfg.gridDim  = dim3(NITEMS, 1, 1);
    cfg.blockDim = dim3(256, 1, 1);
    cfg.dynamicSmemBytes = SMEM_REQ;
    cfg.stream = 0;
    cudaLaunchAttribute attrs[1];
    attrs[0].id = cudaLaunchAttributeProgrammaticStreamSerialization;
    attrs[0].val.programmaticStreamSerializationAllowed = 1;
    cfg.attrs = attrs;
    cfg.numAttrs = 1;
    cudaLaunchKernelEx(&cfg, gemm_mma_kernel, adj);

    reduce_relu_kernel<<<(NN * HID / 4 + 255) / 256, 256>>>(out, b);
}

// round 9
// speedup vs baseline: 1.2558x; 1.0083x over previous
#include <cuda_runtime.h>
#include <cstdint>

#define NN      12000
#define HID     32
#define TSTEPS  50
#define TM      128
#define KSPLIT  3
#define KITEM   4000             // K per work item (KSPLIT*KITEM == NN)
#define NCHUNK  125              // KITEM / 32
#define NBLK    94               // ceil(12000/128)
#define NITEMS  (NBLK * KSPLIT)  // 282 CTAs, one item each
#define NSTAGES 5
#define STAGE_BYTES 20480        // A: 128*32*4 = 16384  +  B: 32*32*4 = 4096
#define SMEM_REQ (NSTAGES * STAGE_BYTES)
#define SGRID   375              // support CTAs (375*32 == 12000)

__device__ float    g_suppT[HID * NN];          // support^T, tf32-rounded
__device__ float    g_part[KSPLIT * NN * HID];  // split-K partials
__device__ unsigned g_scnt;                     // support completions (monotone)
__device__ unsigned g_ticket;                   // gemm CTA tickets (monotone)

// ---------------------------------------------------------------------------
// Kernel 1: support = [z | a_t] @ W, transposed + tf32-rounded output.
// PDL trigger fires FIRST so the GEMM grid launches concurrently; data
// readiness is signalled via the release-increment of g_scnt at the end.
// ---------------------------------------------------------------------------
__global__ void support_kernel(const float* __restrict__ t,
                               const float* __restrict__ z,
                               const float* __restrict__ treat,
                               const float* __restrict__ W) {
    asm volatile("griddepcontrol.launch_dependents;\n" ::: "memory");

    __shared__ float Ws[33 * 32];
    __shared__ float S[32][33];    // stride 33 -> conflict-free transpose
    int tid = threadIdx.x;
    for (int i = tid; i < 33 * 32; i += blockDim.x) Ws[i] = W[i];
    __syncthreads();

    int a_idx = (int)(t[0] * (float)(TSTEPS - 1));
    a_idx = min(max(a_idx, 0), TSTEPS - 1);

    int lane = tid & 31;
    int warp = tid >> 5;
    int row0 = blockIdx.x * 32;
    int r0   = warp * 4;

    float zv[4], acc[4];
#pragma unroll
    for (int j = 0; j < 4; j++) {
        int row = row0 + r0 + j;
        zv[j]  = z[row * 32 + lane];
        acc[j] = treat[row * TSTEPS + a_idx] * Ws[32 * 32 + lane];
    }
#pragma unroll
    for (int k = 0; k < 32; k++) {
        float w = Ws[k * 32 + lane];
#pragma unroll
        for (int j = 0; j < 4; j++) {
            float zk = __shfl_sync(0xffffffffu, zv[j], k);
            acc[j] = fmaf(zk, w, acc[j]);
        }
    }
#pragma unroll
    for (int j = 0; j < 4; j++) {
        uint32_t bits;
        asm("cvt.rna.tf32.f32 %0, %1;" : "=r"(bits) : "f"(acc[j]));
        S[r0 + j][lane] = __uint_as_float(bits);
    }
    __syncthreads();

#pragma unroll
    for (int j = 0; j < 4; j++) {
        int idx = tid + 256 * j;
        int col = idx >> 5;
        int r   = idx & 31;
        g_suppT[col * NN + row0 + r] = S[r][col];
    }

    // release: this CTA's g_suppT slice is globally visible
    __syncthreads();
    if (tid == 0) {
        unsigned old;
        asm volatile("membar.gl;\n" ::: "memory");
        asm volatile("atom.release.gpu.add.u32 %0, [%1], 1;"
                     : "=r"(old) : "l"(&g_scnt) : "memory");
    }
}

// ---------------------------------------------------------------------------
// cp.async stage loads: line-complete per warp-op (whole 128B lines).
// ---------------------------------------------------------------------------
__device__ __forceinline__ void load_A(uint32_t sbase, const float* __restrict__ adj,
                                       int row0, int gk, int tid) {
    int q  = tid & 7;
    int rb = tid >> 3;
#pragma unroll
    for (int i = 0; i < 4; i++) {
        int r = i * 32 + rb;
        const float* src = adj + (long long)(row0 + r) * NN + gk + q * 4;
        uint32_t dst = sbase + r * 128 + (uint32_t)((q ^ (r & 7)) << 4);
        int sz = (row0 + r < NN) ? 16 : 0;
        asm volatile("cp.async.cg.shared.global.L2::256B [%0], [%1], 16, %2;\n"
                     :: "r"(dst), "l"(src), "r"(sz));
    }
}

__device__ __forceinline__ void load_B(uint32_t sbase, int gk, int tid) {
    int q = tid & 7;
    int c = tid >> 3;
    const float* src = g_suppT + (long long)c * NN + gk + q * 4;
    uint32_t dst = sbase + 16384 + c * 128 + (uint32_t)((q ^ (c & 7)) << 4);
    asm volatile("cp.async.cg.shared.global.L2::256B [%0], [%1], 16;\n"
                 :: "r"(dst), "l"(src));
}

// ---------------------------------------------------------------------------
// Kernel 2: tf32 mma.sync GEMM (round-5 body). A-prologue overlaps support;
// acquire-spin on g_scnt replaces griddepcontrol.wait before B loads.
// ---------------------------------------------------------------------------
__global__ void __launch_bounds__(256, 2)
gemm_mma_kernel(const float* __restrict__ adj) {
    extern __shared__ char dsm[];
    uint32_t sbase0 = (uint32_t)__cvta_generic_to_shared(dsm);
    int tid  = threadIdx.x;
    int warp = tid >> 5;
    int lane = tid & 31;
    int g    = lane >> 2;
    int tg   = lane & 3;

    int blk  = blockIdx.x / KSPLIT;
    int kc   = blockIdx.x - blk * KSPLIT;
    int row0 = blk * TM;
    int k0   = kc * KITEM;

    // A-only prologue (adj independent of support)
#pragma unroll
    for (int p = 0; p < NSTAGES - 1; p++) {
        load_A(sbase0 + p * STAGE_BYTES, adj, row0, k0 + p * 32, tid);
        asm volatile("cp.async.commit_group;\n" ::: "memory");
    }

    // acquire support data: wait until all SGRID support CTAs of THIS replay
    // have released. Replay index derived from a monotone gemm ticket.
    if (tid == 0) {
        unsigned old;
        asm volatile("atom.relaxed.gpu.add.u32 %0, [%1], 1;"
                     : "=r"(old) : "l"(&g_ticket) : "memory");
        unsigned target = (old / NITEMS + 1u) * SGRID;
        unsigned cur;
        do {
            asm volatile("ld.acquire.gpu.u32 %0, [%1];"
                         : "=r"(cur) : "l"(&g_scnt) : "memory");
        } while (cur < target);
    }
    __syncthreads();

    // B prologue
#pragma unroll
    for (int p = 0; p < NSTAGES - 1; p++) {
        load_B(sbase0 + p * STAGE_BYTES, k0 + p * 32, tid);
        asm volatile("cp.async.commit_group;\n" ::: "memory");
    }

    float acc[4][4];
#pragma unroll
    for (int n = 0; n < 4; n++)
#pragma unroll
        for (int i = 0; i < 4; i++) acc[n][i] = 0.f;

    const uint32_t aoff = (uint32_t)(warp * 16 + g) * 128 + tg * 4;
    const uint32_t boff = 16384u + (uint32_t)g * 128 + tg * 4;

    for (int c = 0; c < NCHUNK; c++) {
        asm volatile("cp.async.wait_group 3;\n" ::: "memory");
        __syncthreads();

        if (c + NSTAGES - 1 < NCHUNK) {
            uint32_t sb = sbase0 + ((c + NSTAGES - 1) % NSTAGES) * STAGE_BYTES;
            load_A(sb, adj, row0, k0 + (c + NSTAGES - 1) * 32, tid);
            load_B(sb, k0 + (c + NSTAGES - 1) * 32, tid);
        }
        asm volatile("cp.async.commit_group;\n" ::: "memory");

        const char* st = dsm + (c % NSTAGES) * STAGE_BYTES;
#pragma unroll
        for (int ks = 0; ks < 4; ks++) {
            uint32_t q0 = (uint32_t)(((2 * ks) ^ g) << 4);
            uint32_t q1 = (uint32_t)(((2 * ks + 1) ^ g) << 4);

            uint32_t a0 = *(const uint32_t*)(st + aoff + q0);
            uint32_t a2 = *(const uint32_t*)(st + aoff + q1);
            uint32_t a1 = *(const uint32_t*)(st + aoff + 1024 + q0);
            uint32_t a3 = *(const uint32_t*)(st + aoff + 1024 + q1);
#pragma unroll
            for (int nt = 0; nt < 4; nt++) {
                uint32_t b0 = *(const uint32_t*)(st + boff + nt * 1024 + q0);
                uint32_t b1 = *(const uint32_t*)(st + boff + nt * 1024 + q1);
                asm volatile(
                    "mma.sync.aligned.m16n8k8.row.col.f32.tf32.tf32.f32 "
                    "{%0,%1,%2,%3}, {%4,%5,%6,%7}, {%8,%9}, {%0,%1,%2,%3};\n"
                    : "+f"(acc[nt][0]), "+f"(acc[nt][1]),
                      "+f"(acc[nt][2]), "+f"(acc[nt][3])
                    : "r"(a0), "r"(a1), "r"(a2), "r"(a3), "r"(b0), "r"(b1));
            }
        }
    }

    float* part = g_part + (long long)kc * (NN * HID);
    int r_lo = row0 + warp * 16 + g;
    int r_hi = r_lo + 8;
#pragma unroll
    for (int nt = 0; nt < 4; nt++) {
        int colb = nt * 8 + 2 * tg;
        if (r_lo < NN)
            *(float2*)(part + (long long)r_lo * HID + colb) =
                make_float2(acc[nt][0], acc[nt][1]);
        if (r_hi < NN)
            *(float2*)(part + (long long)r_hi * HID + colb) =
                make_float2(acc[nt][2], acc[nt][3]);
    }
}

// ---------------------------------------------------------------------------
// Kernel 3: out = relu(sum_kc part[kc] + b)
// ---------------------------------------------------------------------------
__global__ void reduce_relu_kernel(float* __restrict__ out,
                                   const float* __restrict__ b) {
    int i4 = blockIdx.x * blockDim.x + threadIdx.x;
    if (i4 >= NN * HID / 4) return;
    const float4* p = (const float4*)g_part;
    float4 s = ((const float4*)b)[i4 & 7];
#pragma unroll
    for (int kc = 0; kc < KSPLIT; kc++) {
        float4 v = p[(long long)kc * (NN * HID / 4) + i4];
        s.x += v.x; s.y += v.y; s.z += v.z; s.w += v.w;
    }
    float4 r;
    r.x = fmaxf(s.x, 0.f);
    r.y = fmaxf(s.y, 0.f);
    r.z = fmaxf(s.z, 0.f);
    r.w = fmaxf(s.w, 0.f);
    ((float4*)out)[i4] = r;
}

// ---------------------------------------------------------------------------
extern "C" void kernel_launch(void* const* d_in, const int* in_sizes, int n_in,
                              void* d_out, int out_size) {
    (void)in_sizes; (void)n_in; (void)out_size;
    const float* t     = (const float*)d_in[0];
    const float* z     = (const float*)d_in[1];
    const float* adj   = (const float*)d_in[2];
    const float* treat = (const float*)d_in[3];
    const float* W     = (const float*)d_in[4];
    const float* b     = (const float*)d_in[5];
    float* out = (float*)d_out;

    cudaFuncSetAttribute(gemm_mma_kernel,
                         cudaFuncAttributeMaxDynamicSharedMemorySize, SMEM_REQ);

    support_kernel<<<SGRID, 256>>>(t, z, treat, W);

    cudaLaunchConfig_t cfg = {};
    cfg.gridDim  = dim3(NITEMS, 1, 1);
    cfg.blockDim = dim3(256, 1, 1);
    cfg.dynamicSmemBytes = SMEM_REQ;
    cfg.stream = 0;
    cudaLaunchAttribute attrs[1];
    attrs[0].id = cudaLaunchAttributeProgrammaticStreamSerialization;
    attrs[0].val.programmaticStreamSerializationAllowed = 1;
    cfg.attrs = attrs;
    cfg.numAttrs = 1;
    cudaLaunchKernelEx(&cfg, gemm_mma_kernel, adj);

    reduce_relu_kernel<<<(NN * HID / 4 + 255) / 256, 256>>>(out, b);
}